// round 4
// baseline (speedup 1.0000x reference)
#include <cuda_runtime.h>
#include <math.h>
#include <stdint.h>

// Problem constants
#define Dm   2048
#define Nh   16
#define Kh   8
#define Hd   128
#define Ff   8192
#define Bb   2
#define T0c  1024
#define T1c  1024
#define TOTc 2048

// ---------------- scratch (static device globals; no allocation) ----------
__device__ float g_pre [(size_t)Bb*TOTc*Dm];
__device__ float g_q   [(size_t)Bb*TOTc*Nh*Hd];
__device__ float g_k   [(size_t)Bb*TOTc*Kh*Hd];
__device__ float g_v   [(size_t)Bb*TOTc*Kh*Hd];
__device__ float g_enc [(size_t)Bb*TOTc*Nh*Hd];
__device__ float g_res [(size_t)Bb*TOTc*Dm];
__device__ float g_hid [(size_t)Bb*TOTc*Dm];
__device__ float g_gu  [(size_t)2*Bb*T0c*Ff];

__device__ __forceinline__ unsigned f2tf32(float x) {
    unsigned r;
    asm("cvt.rna.tf32.f32 %0, %1;" : "=r"(r) : "f"(x));
    return r;
}

__device__ __forceinline__ void mma8(float* c, const unsigned* a, unsigned b0, unsigned b1) {
    asm volatile(
        "mma.sync.aligned.m16n8k8.row.col.f32.tf32.tf32.f32 "
        "{%0,%1,%2,%3},{%4,%5,%6,%7},{%8,%9},{%0,%1,%2,%3};"
        : "+f"(c[0]), "+f"(c[1]), "+f"(c[2]), "+f"(c[3])
        : "r"(a[0]), "r"(a[1]), "r"(a[2]), "r"(a[3]), "r"(b0), "r"(b1));
}

__device__ __forceinline__ float gelu_t(float x) {
    float x3 = x * x * x;
    float t = tanhf(0.7978845608028654f * (x + 0.044715f * x3));
    return 0.5f * x * (1.f + t);
}

__device__ __forceinline__ void cpasync16(float* s, const float* g) {
    unsigned saddr = (unsigned)__cvta_generic_to_shared(s);
    asm volatile("cp.async.cg.shared.global [%0], [%1], 16;" :: "r"(saddr), "l"(g));
}

// swizzled float offset for element (row r, col c) in a 128x16 tile,
// 64B rows grouped into 128B blocks, chunk XOR swizzle (conflict-free frags)
__device__ __forceinline__ int swoff(int r, int c) {
    return ((r >> 1) << 5) + (((((r & 1) << 2) | (c >> 2)) ^ ((r >> 1) & 7)) << 2) + (c & 3);
}

// ---------------- RMSNorm ----------------
__device__ __forceinline__ int maprow(int r, int T, int TT, int off) {
    return (r / T) * TT + (r % T) + off;
}

__global__ void rmsnorm_k(const float* __restrict__ x, const float* __restrict__ sc,
                          float* __restrict__ out,
                          int iT, int iTT, int iOff, int oT, int oTT, int oOff)
{
    int r = blockIdx.x;
    const float* xi = x + (size_t)maprow(r, iT, iTT, iOff) * Dm;
    float* o = out + (size_t)maprow(r, oT, oTT, oOff) * Dm;
    __shared__ float red[256];
    float s = 0.f;
    for (int d = threadIdx.x; d < Dm; d += 256) { float v = xi[d]; s += v * v; }
    red[threadIdx.x] = s;
    __syncthreads();
    for (int st = 128; st > 0; st >>= 1) {
        if (threadIdx.x < st) red[threadIdx.x] += red[threadIdx.x + st];
        __syncthreads();
    }
    float inv = rsqrtf(red[0] / (float)Dm + 1e-6f);
    for (int d = threadIdx.x; d < Dm; d += 256)
        o[d] = xi[d] * inv * (1.f + sc[d]);
}

// ---------------- RoPE ----------------
__global__ void rope_k(float* __restrict__ x, const int* __restrict__ pos,
                       int nheads, float scale)
{
    int blk  = blockIdx.x;
    int head = blk % nheads;
    int bt   = blk / nheads;
    float p  = (float)pos[bt];
    float* v = x + ((size_t)bt * nheads + head) * Hd;
    int h = threadIdx.x;               // 0..63
    float fe = (2.f / (float)Hd) * (float)h;
    float inv_ts = exp2f(-fe * 13.287712379549449f);
    float rad = p * inv_ts;
    float s, c;
    sincosf(rad, &s, &c);
    float x1 = v[h], x2 = v[h + 64];
    v[h]      = (x1 * c - x2 * s) * scale;
    v[h + 64] = (x2 * c + x1 * s) * scale;
}

// ---------------- tf32 GEMM body, cp.async 3-stage pipeline ----------------
// CTA tile 128x128, BK=16. 8 warps = 2m x 4n, warp tile 64x32.
// mode: 0 = C=acc ; 1 = C=acc+R ; 2 = C=gelu(R)*acc
#define NSTAGE 3
#define TILEF  (128 * 16)
__device__ __forceinline__ void gemm_body(
    const float* __restrict__ A, const float* __restrict__ Wt,
    float* __restrict__ C, const float* __restrict__ R,
    int Kin, int NoutC,
    int aRow0, int wRow0, int cRow0, int rRow0, int cCol0, int mode,
    float* __restrict__ Asf, float* __restrict__ Bsf)
{
    const int tid  = threadIdx.x;
    const int warp = tid >> 5, lane = tid & 31;
    const int wm   = (warp & 1) * 64;
    const int wn   = (warp >> 1) * 32;
    const int r0   = lane >> 2, c0 = lane & 3;

    // cp.async mapping: thread t -> row t>>1, chunks c2,c2+1 (16B each)
    const int row = tid >> 1;
    const int c2  = (tid & 1) << 1;
    const float* aRow = A  + (size_t)(aRow0 + row) * Kin + (c2 << 2);
    const float* wRow = Wt + (size_t)(wRow0 + row) * Kin + (c2 << 2);
    const int base128 = (row >> 1) << 5;
    const int xr = (row >> 1) & 7;
    const int rb = (row & 1) << 2;
    const int dA0 = base128 + (((rb |  c2)      ^ xr) << 2);
    const int dA1 = base128 + (((rb | (c2 + 1)) ^ xr) << 2);

    float acc[4][4][4];
#pragma unroll
    for (int mt = 0; mt < 4; mt++)
#pragma unroll
        for (int nt = 0; nt < 4; nt++)
#pragma unroll
            for (int i = 0; i < 4; i++) acc[mt][nt][i] = 0.f;

    const int nk = Kin / 16;

    // prologue: prefetch tiles 0..NSTAGE-2
#pragma unroll
    for (int s = 0; s < NSTAGE - 1; s++) {
        float* ad = Asf + s * TILEF;
        float* bd = Bsf + s * TILEF;
        const float* ag = aRow + s * 16;
        const float* bg = wRow + s * 16;
        cpasync16(ad + dA0, ag);
        cpasync16(ad + dA1, ag + 4);
        cpasync16(bd + dA0, bg);
        cpasync16(bd + dA1, bg + 4);
        asm volatile("cp.async.commit_group;");
    }

    int buf = 0, pbuf = NSTAGE - 1;
    for (int kt = 0; kt < nk; kt++) {
        asm volatile("cp.async.wait_group %0;" :: "n"(NSTAGE - 2));
        __syncthreads();

        // issue prefetch for tile kt+NSTAGE-1
        int pf = kt + NSTAGE - 1;
        if (pf < nk) {
            float* ad = Asf + pbuf * TILEF;
            float* bd = Bsf + pbuf * TILEF;
            const float* ag = aRow + pf * 16;
            const float* bg = wRow + pf * 16;
            cpasync16(ad + dA0, ag);
            cpasync16(ad + dA1, ag + 4);
            cpasync16(bd + dA0, bg);
            cpasync16(bd + dA1, bg + 4);
        }
        asm volatile("cp.async.commit_group;");
        if (++pbuf == NSTAGE) pbuf = 0;

        const float* as = Asf + buf * TILEF;
        const float* bs = Bsf + buf * TILEF;
        if (++buf == NSTAGE) buf = 0;

#pragma unroll
        for (int ks = 0; ks < 2; ks++) {
            unsigned af[4][4], bf[4][2];
            const int col = ks * 8 + c0;
#pragma unroll
            for (int mt = 0; mt < 4; mt++) {
                int r = wm + mt * 16 + r0;
                af[mt][0] = f2tf32(as[swoff(r,     col)]);
                af[mt][1] = f2tf32(as[swoff(r + 8, col)]);
                af[mt][2] = f2tf32(as[swoff(r,     col + 4)]);
                af[mt][3] = f2tf32(as[swoff(r + 8, col + 4)]);
            }
#pragma unroll
            for (int nt = 0; nt < 4; nt++) {
                int r = wn + nt * 8 + r0;
                bf[nt][0] = f2tf32(bs[swoff(r, col)]);
                bf[nt][1] = f2tf32(bs[swoff(r, col + 4)]);
            }
#pragma unroll
            for (int mt = 0; mt < 4; mt++)
#pragma unroll
                for (int nt = 0; nt < 4; nt++)
                    mma8(acc[mt][nt], af[mt], bf[nt][0], bf[nt][1]);
        }
        __syncthreads();
    }

    // epilogue
#pragma unroll
    for (int mt = 0; mt < 4; mt++) {
        int rl = wm + mt * 16 + r0;
#pragma unroll
        for (int nt = 0; nt < 4; nt++) {
            int cc = cCol0 + wn + nt * 8 + 2 * c0;
            float2 v0 = make_float2(acc[mt][nt][0], acc[mt][nt][1]);
            float2 v1 = make_float2(acc[mt][nt][2], acc[mt][nt][3]);
            if (mode == 1) {
                float2 u0 = *(const float2*)&R[(size_t)(rRow0 + rl) * NoutC + cc];
                float2 u1 = *(const float2*)&R[(size_t)(rRow0 + rl + 8) * NoutC + cc];
                v0.x += u0.x; v0.y += u0.y;
                v1.x += u1.x; v1.y += u1.y;
            } else if (mode == 2) {
                float2 u0 = *(const float2*)&R[(size_t)(rRow0 + rl) * NoutC + cc];
                float2 u1 = *(const float2*)&R[(size_t)(rRow0 + rl + 8) * NoutC + cc];
                v0.x *= gelu_t(u0.x); v0.y *= gelu_t(u0.y);
                v1.x *= gelu_t(u1.x); v1.y *= gelu_t(u1.y);
            }
            *(float2*)&C[(size_t)(cRow0 + rl) * NoutC + cc]     = v0;
            *(float2*)&C[(size_t)(cRow0 + rl + 8) * NoutC + cc] = v1;
        }
    }
}

// -------- fused QKV: grid (32 n-tiles, 16 m-tiles, 2 segments) ------------
__global__ __launch_bounds__(256, 2)
void qkv_tc(const float* __restrict__ qw0, const float* __restrict__ qw1,
            const float* __restrict__ kw0, const float* __restrict__ kw1,
            const float* __restrict__ vw0, const float* __restrict__ vw1)
{
    __shared__ float As[NSTAGE * TILEF];
    __shared__ float Bs[NSTAGE * TILEF];
    int bn = blockIdx.x, bm = blockIdx.y * 128, z = blockIdx.z;
    const float* Wt;
    float* C;
    int NoutC, wRow0;
    if (bn < 16) {
        Wt = z ? qw1 : qw0; C = g_q; NoutC = Nh * Hd; wRow0 = bn * 128;
    } else if (bn < 24) {
        Wt = z ? kw1 : kw0; C = g_k; NoutC = Kh * Hd; wRow0 = (bn - 16) * 128;
    } else {
        Wt = z ? vw1 : vw0; C = g_v; NoutC = Kh * Hd; wRow0 = (bn - 24) * 128;
    }
    int rowTOT = bm + (bm >> 10) * 1024 + z * 1024;
    gemm_body(g_pre, Wt, C, nullptr, Dm, NoutC,
              rowTOT, wRow0, rowTOT, 0, wRow0, 0, As, Bs);
}

// -------- generic fused-2-segment GEMM ------------------------------------
// row layout codes: 0 = [B,TOT] interleaved ; 1 = contiguous per-seg ; 2 = per-seg local
__global__ __launch_bounds__(256, 2)
void gemm_z(const float* __restrict__ A,
            const float* __restrict__ W0, const float* __restrict__ W1,
            float* __restrict__ C,
            const float* __restrict__ R0, const float* __restrict__ R1,
            int Kin, int NoutC, int mode, int aLay, int cLay, int rLay)
{
    __shared__ float As[NSTAGE * TILEF];
    __shared__ float Bs[NSTAGE * TILEF];
    int bn = blockIdx.x, bm = blockIdx.y * 128, z = blockIdx.z;
    const float* Wt = z ? W1 : W0;
    const float* R  = z ? R1 : R0;
    int rowTOT = bm + (bm >> 10) * 1024 + z * 1024;
    int rowSEG = z * 2048 + bm;
    int aRow0 = (aLay == 0) ? rowTOT : (aLay == 1 ? rowSEG : bm);
    int cRow0 = (cLay == 0) ? rowTOT : (cLay == 1 ? rowSEG : bm);
    int rRow0 = (rLay == 0) ? rowTOT : (rLay == 1 ? rowSEG : bm);
    gemm_body(A, Wt, C, R, Kin, NoutC,
              aRow0, bn * 128, cRow0, rRow0, bn * 128, mode, As, Bs);
}

// ---------------- attention: flash-style, tf32 mma ----------------
#define ATQ 64
#define ATS 32
#define KVP 136
#define PSP 36
__global__ __launch_bounds__(128, 2)
void attn_tc(const float* __restrict__ Q, const float* __restrict__ Kb,
             const float* __restrict__ Vb, float* __restrict__ enc)
{
    __shared__ unsigned Ks[ATS * KVP];
    __shared__ unsigned Vs[ATS * KVP];
    __shared__ unsigned Ps[4][16 * PSP];

    const int b = blockIdx.z, n = blockIdx.y;
    const int tq0 = blockIdx.x * ATQ;
    const int kh = n >> 1;   // G = 2
    const int tid = threadIdx.x, warp = tid >> 5, lane = tid & 31;
    const int r0 = lane >> 2, c0 = lane & 3;
    const int trowA = tq0 + warp * 16 + r0;

    unsigned qf[16][4];
    {
        const float* qbase = Q + ((size_t)(b * TOTc + tq0 + warp * 16)) * (Nh * Hd)
                               + (size_t)n * Hd;
        const size_t rs = (size_t)Nh * Hd;
#pragma unroll
        for (int hc = 0; hc < 16; hc++) {
            int col = hc * 8 + c0;
            const float* p0 = qbase + (size_t)r0 * rs + col;
            const float* p1 = qbase + (size_t)(r0 + 8) * rs + col;
            qf[hc][0] = f2tf32(p0[0]);
            qf[hc][1] = f2tf32(p1[0]);
            qf[hc][2] = f2tf32(p0[4]);
            qf[hc][3] = f2tf32(p1[4]);
        }
    }

    float oacc[16][4];
#pragma unroll
    for (int ht = 0; ht < 16; ht++)
#pragma unroll
        for (int i = 0; i < 4; i++) oacc[ht][i] = 0.f;
    float mA = -3.0e38f, mB = -3.0e38f, lA = 0.f, lB = 0.f;

    const int tmax = tq0 + ATQ - 1;

    for (int s0 = 0; s0 <= tmax; s0 += ATS) {
        for (int i = tid; i < ATS * Hd / 4; i += 128) {
            int sr = (i * 4) >> 7;
            int cl = (i * 4) & 127;
            size_t g = ((size_t)(b * TOTc + s0 + sr)) * (Kh * Hd) + (size_t)kh * Hd + cl;
            float4 kv = *(const float4*)&Kb[g];
            float4 vv = *(const float4*)&Vb[g];
            *(uint4*)&Ks[sr * KVP + cl] =
                make_uint4(f2tf32(kv.x), f2tf32(kv.y), f2tf32(kv.z), f2tf32(kv.w));
            *(uint4*)&Vs[sr * KVP + cl] =
                make_uint4(f2tf32(vv.x), f2tf32(vv.y), f2tf32(vv.z), f2tf32(vv.w));
        }
        __syncthreads();

        float sacc[4][4];
#pragma unroll
        for (int nt = 0; nt < 4; nt++)
#pragma unroll
            for (int i = 0; i < 4; i++) sacc[nt][i] = 0.f;
#pragma unroll
        for (int hc = 0; hc < 16; hc++) {
#pragma unroll
            for (int nt = 0; nt < 4; nt++) {
                unsigned b0 = Ks[(nt * 8 + r0) * KVP + hc * 8 + c0];
                unsigned b1 = Ks[(nt * 8 + r0) * KVP + hc * 8 + c0 + 4];
                mma8(sacc[nt], qf[hc], b0, b1);
            }
        }

        if (s0 + ATS - 1 > tq0 + warp * 16) {
#pragma unroll
            for (int nt = 0; nt < 4; nt++) {
                int sA = s0 + nt * 8 + 2 * c0;
                if (sA     > trowA)     sacc[nt][0] = -3.0e38f;
                if (sA + 1 > trowA)     sacc[nt][1] = -3.0e38f;
                if (sA     > trowA + 8) sacc[nt][2] = -3.0e38f;
                if (sA + 1 > trowA + 8) sacc[nt][3] = -3.0e38f;
            }
        }

        float mx0 = fmaxf(fmaxf(sacc[0][0], sacc[0][1]), fmaxf(sacc[1][0], sacc[1][1]));
        mx0 = fmaxf(mx0, fmaxf(fmaxf(sacc[2][0], sacc[2][1]), fmaxf(sacc[3][0], sacc[3][1])));
        float mx1 = fmaxf(fmaxf(sacc[0][2], sacc[0][3]), fmaxf(sacc[1][2], sacc[1][3]));
        mx1 = fmaxf(mx1, fmaxf(fmaxf(sacc[2][2], sacc[2][3]), fmaxf(sacc[3][2], sacc[3][3])));
#pragma unroll
        for (int o = 1; o <= 2; o <<= 1) {
            mx0 = fmaxf(mx0, __shfl_xor_sync(0xffffffffu, mx0, o));
            mx1 = fmaxf(mx1, __shfl_xor_sync(0xffffffffu, mx1, o));
        }
        float nmA = fmaxf(mA, mx0), nmB = fmaxf(mB, mx1);
        float scA = __expf(mA - nmA), scB = __expf(mB - nmB);
        mA = nmA; mB = nmB;

        float s0A = 0.f, s0B = 0.f;
        unsigned* pw = Ps[warp];
#pragma unroll
        for (int nt = 0; nt < 4; nt++) {
            float p0 = __expf(sacc[nt][0] - nmA);
            float p1 = __expf(sacc[nt][1] - nmA);
            float p2 = __expf(sacc[nt][2] - nmB);
            float p3 = __expf(sacc[nt][3] - nmB);
            s0A += p0 + p1; s0B += p2 + p3;
            int col = nt * 8 + 2 * c0;
            pw[r0 * PSP + col]           = f2tf32(p0);
            pw[r0 * PSP + col + 1]       = f2tf32(p1);
            pw[(r0 + 8) * PSP + col]     = f2tf32(p2);
            pw[(r0 + 8) * PSP + col + 1] = f2tf32(p3);
        }
#pragma unroll
        for (int o = 1; o <= 2; o <<= 1) {
            s0A += __shfl_xor_sync(0xffffffffu, s0A, o);
            s0B += __shfl_xor_sync(0xffffffffu, s0B, o);
        }
        lA = lA * scA + s0A;
        lB = lB * scB + s0B;

#pragma unroll
        for (int ht = 0; ht < 16; ht++) {
            oacc[ht][0] *= scA; oacc[ht][1] *= scA;
            oacc[ht][2] *= scB; oacc[ht][3] *= scB;
        }
        __syncwarp();

#pragma unroll
        for (int kc = 0; kc < 4; kc++) {
            unsigned af[4];
            af[0] = pw[r0 * PSP + kc * 8 + c0];
            af[1] = pw[(r0 + 8) * PSP + kc * 8 + c0];
            af[2] = pw[r0 * PSP + kc * 8 + c0 + 4];
            af[3] = pw[(r0 + 8) * PSP + kc * 8 + c0 + 4];
#pragma unroll
            for (int ht = 0; ht < 16; ht++) {
                unsigned b0 = Vs[(kc * 8 + c0) * KVP + ht * 8 + r0];
                unsigned b1 = Vs[(kc * 8 + c0 + 4) * KVP + ht * 8 + r0];
                mma8(oacc[ht], af, b0, b1);
            }
        }
        __syncthreads();
    }

    float invA = 1.f / lA, invB = 1.f / lB;
    const size_t baseA = ((size_t)(b * TOTc + trowA)) * (Nh * Hd) + (size_t)n * Hd;
    const size_t baseB = ((size_t)(b * TOTc + trowA + 8)) * (Nh * Hd) + (size_t)n * Hd;
#pragma unroll
    for (int ht = 0; ht < 16; ht++) {
        int cc = ht * 8 + 2 * c0;
        *(float2*)&enc[baseA + cc] = make_float2(oacc[ht][0] * invA, oacc[ht][1] * invA);
        *(float2*)&enc[baseB + cc] = make_float2(oacc[ht][2] * invB, oacc[ht][3] * invB);
    }
}

// ---------------- host orchestration ----------------
extern "C" void kernel_launch(void* const* d_in, const int* in_sizes, int n_in,
                              void* d_out, int out_size)
{
    (void)in_sizes; (void)n_in; (void)out_size;
    const float* xs[2] = {(const float*)d_in[0], (const float*)d_in[1]};
    const int*   pos   = (const int*)d_in[2];
    // d_in[3] = mask: causal lower-triangular, computed in-kernel
    const float* qw[2] = {(const float*)d_in[4],  (const float*)d_in[5]};
    const float* kw[2] = {(const float*)d_in[6],  (const float*)d_in[7]};
    const float* vw[2] = {(const float*)d_in[8],  (const float*)d_in[9]};
    const float* ow[2] = {(const float*)d_in[10], (const float*)d_in[11]};
    const float* gw[2] = {(const float*)d_in[12], (const float*)d_in[13]};
    const float* uw[2] = {(const float*)d_in[14], (const float*)d_in[15]};
    const float* dwn[2]= {(const float*)d_in[16], (const float*)d_in[17]};
    const float* pa[2] = {(const float*)d_in[18], (const float*)d_in[19]};
    const float* pf[2] = {(const float*)d_in[20], (const float*)d_in[21]};
    float* out = (float*)d_out;

    float *pre, *qb, *kb, *vb, *enc, *res, *hid, *gu;
    cudaGetSymbolAddress((void**)&pre, g_pre);
    cudaGetSymbolAddress((void**)&qb,  g_q);
    cudaGetSymbolAddress((void**)&kb,  g_k);
    cudaGetSymbolAddress((void**)&vb,  g_v);
    cudaGetSymbolAddress((void**)&enc, g_enc);
    cudaGetSymbolAddress((void**)&res, g_res);
    cudaGetSymbolAddress((void**)&hid, g_hid);
    cudaGetSymbolAddress((void**)&gu,  g_gu);

    const int Ts[2]   = {T0c, T1c};
    const int offs[2] = {0, T0c};

    // 1) pre-attention RMSNorm
    for (int s = 0; s < 2; s++)
        rmsnorm_k<<<Bb * Ts[s], 256>>>(xs[s], pa[s], pre,
                                       Ts[s], Ts[s], 0, Ts[s], TOTc, offs[s]);

    // 2) fused QKV projection, both segments
    qkv_tc<<<dim3(32, 16, 2), 256>>>(qw[0], qw[1], kw[0], kw[1], vw[0], vw[1]);

    // 3) RoPE (Q gets 1/sqrt(H) folded in)
    rope_k<<<Bb * TOTc * Nh, 64>>>(qb, pos, Nh, 0.08838834764831845f);
    rope_k<<<Bb * TOTc * Kh, 64>>>(kb, pos, Kh, 1.0f);

    // 4) attention (tensor-core flash)
    attn_tc<<<dim3(TOTc / ATQ, Nh, Bb), 128>>>(qb, kb, vb, enc);

    // 5) O projection + residual add of x
    gemm_z<<<dim3(Dm / 128, 16, 2), 256>>>(enc, ow[0], ow[1], res, xs[0], xs[1],
                                           Nh * Hd, Dm, 1, 0, 0, 2);

    // 6) pre-FFN RMSNorm
    for (int s = 0; s < 2; s++)
        rmsnorm_k<<<Bb * Ts[s], 256>>>(res, pf[s], hid,
                                       Ts[s], TOTc, offs[s], Ts[s], TOTc, offs[s]);

    // 7) FFN: gate -> gu ; up (epilogue gelu(gate)*up) -> gu ; down + residual -> out
    gemm_z<<<dim3(Ff / 128, 16, 2), 256>>>(hid, gw[0], gw[1], gu, nullptr, nullptr,
                                           Dm, Ff, 0, 0, 1, 1);
    gemm_z<<<dim3(Ff / 128, 16, 2), 256>>>(hid, uw[0], uw[1], gu, gu, gu,
                                           Dm, Ff, 2, 0, 1, 1);
    gemm_z<<<dim3(Dm / 128, 16, 2), 256>>>(gu, dwn[0], dwn[1], out, res, res,
                                           Ff, Dm, 1, 1, 1, 0);
}

// round 5
// speedup vs baseline: 1.2219x; 1.2219x over previous
#include <cuda_runtime.h>
#include <math.h>
#include <stdint.h>

// Problem constants
#define Dm   2048
#define Nh   16
#define Kh   8
#define Hd   128
#define Ff   8192
#define Bb   2
#define T0c  1024
#define T1c  1024
#define TOTc 2048

// ---------------- scratch (static device globals; no allocation) ----------
__device__ float g_pre [(size_t)Bb*TOTc*Dm];
__device__ float g_q   [(size_t)Bb*TOTc*Nh*Hd];
__device__ float g_k   [(size_t)Bb*TOTc*Kh*Hd];
__device__ float g_v   [(size_t)Bb*TOTc*Kh*Hd];
__device__ float g_enc [(size_t)Bb*TOTc*Nh*Hd];
__device__ float g_res [(size_t)Bb*TOTc*Dm];
__device__ float g_hid [(size_t)Bb*TOTc*Dm];
__device__ float g_gu  [(size_t)2*Bb*T0c*Ff];
// rounded weight copies (tf32-RNA applied once)
#define WQ  (2048 * 2048)
#define WK  (1024 * 2048)
#define WF  (8192 * 2048)
#define WSEG (WQ + WK + WK + WQ + WF + WF + WF)
__device__ float g_wts [(size_t)2 * WSEG];

__device__ __forceinline__ unsigned f2tf32(float x) {
    unsigned r;
    asm("cvt.rna.tf32.f32 %0, %1;" : "=r"(r) : "f"(x));
    return r;
}
__device__ __forceinline__ float roundtf(float x) {
    return __uint_as_float(f2tf32(x));
}

__device__ __forceinline__ void mma8(float* c, const unsigned* a, unsigned b0, unsigned b1) {
    asm volatile(
        "mma.sync.aligned.m16n8k8.row.col.f32.tf32.tf32.f32 "
        "{%0,%1,%2,%3},{%4,%5,%6,%7},{%8,%9},{%0,%1,%2,%3};"
        : "+f"(c[0]), "+f"(c[1]), "+f"(c[2]), "+f"(c[3])
        : "r"(a[0]), "r"(a[1]), "r"(a[2]), "r"(a[3]), "r"(b0), "r"(b1));
}

__device__ __forceinline__ float gelu_t(float x) {
    float x3 = x * x * x;
    float t = tanhf(0.7978845608028654f * (x + 0.044715f * x3));
    return 0.5f * x * (1.f + t);
}

__device__ __forceinline__ void cpasync16(float* s, const float* g) {
    unsigned saddr = (unsigned)__cvta_generic_to_shared(s);
    asm volatile("cp.async.cg.shared.global [%0], [%1], 16;" :: "r"(saddr), "l"(g));
}

// swizzled float offset for element (row r, col c) in a 128x16 tile
__device__ __forceinline__ int swoff(int r, int c) {
    return ((r >> 1) << 5) + (((((r & 1) << 2) | (c >> 2)) ^ ((r >> 1) & 7)) << 2) + (c & 3);
}

// ---------------- weight rounding prep ----------------
__global__ void roundcp_k(const float4* __restrict__ in, float4* __restrict__ out, int n4)
{
    int i = blockIdx.x * 256 + threadIdx.x;
    if (i >= n4) return;
    float4 v = in[i];
    v.x = roundtf(v.x); v.y = roundtf(v.y);
    v.z = roundtf(v.z); v.w = roundtf(v.w);
    out[i] = v;
}

// ---------------- RMSNorm (output rounded to tf32 grid) ----------------
__device__ __forceinline__ int maprow(int r, int T, int TT, int off) {
    return (r / T) * TT + (r % T) + off;
}

__global__ void rmsnorm_k(const float* __restrict__ x, const float* __restrict__ sc,
                          float* __restrict__ out,
                          int iT, int iTT, int iOff, int oT, int oTT, int oOff)
{
    int r = blockIdx.x;
    const float* xi = x + (size_t)maprow(r, iT, iTT, iOff) * Dm;
    float* o = out + (size_t)maprow(r, oT, oTT, oOff) * Dm;
    __shared__ float red[256];
    float s = 0.f;
    for (int d = threadIdx.x; d < Dm; d += 256) { float v = xi[d]; s += v * v; }
    red[threadIdx.x] = s;
    __syncthreads();
    for (int st = 128; st > 0; st >>= 1) {
        if (threadIdx.x < st) red[threadIdx.x] += red[threadIdx.x + st];
        __syncthreads();
    }
    float inv = rsqrtf(red[0] / (float)Dm + 1e-6f);
    for (int d = threadIdx.x; d < Dm; d += 256)
        o[d] = roundtf(xi[d] * inv * (1.f + sc[d]));
}

// ---------------- RoPE ----------------
__global__ void rope_k(float* __restrict__ x, const int* __restrict__ pos,
                       int nheads, float scale)
{
    int blk  = blockIdx.x;
    int head = blk % nheads;
    int bt   = blk / nheads;
    float p  = (float)pos[bt];
    float* v = x + ((size_t)bt * nheads + head) * Hd;
    int h = threadIdx.x;               // 0..63
    float fe = (2.f / (float)Hd) * (float)h;
    float inv_ts = exp2f(-fe * 13.287712379549449f);
    float rad = p * inv_ts;
    float s, c;
    sincosf(rad, &s, &c);
    float x1 = v[h], x2 = v[h + 64];
    v[h]      = (x1 * c - x2 * s) * scale;
    v[h + 64] = (x2 * c + x1 * s) * scale;
}

// ---------------- tf32 GEMM body: cp.async 3-stage, 1 barrier, no cvt -----
// CTA tile 128x128, BK=16. 8 warps = 2m x 4n, warp tile 64x32.
// mode: 0 = C=acc ; 1 = C=acc+R ; 2 = C=round(gelu(R)*acc)
#define NSTAGE 3
#define TILEF  (128 * 16)
__device__ __forceinline__ void gemm_body(
    const float* __restrict__ A, const float* __restrict__ Wt,
    float* __restrict__ C, const float* __restrict__ R,
    int Kin, int NoutC,
    int aRow0, int wRow0, int cRow0, int rRow0, int cCol0, int mode,
    float* __restrict__ Asf, float* __restrict__ Bsf)
{
    const int tid  = threadIdx.x;
    const int warp = tid >> 5, lane = tid & 31;
    const int wm   = (warp & 1) * 64;
    const int wn   = (warp >> 1) * 32;
    const int r0   = lane >> 2, c0 = lane & 3;

    // cp.async mapping: thread t -> row t>>1, two 16B chunks
    const int row = tid >> 1;
    const int c2  = (tid & 1) << 1;
    const float* aRow = A  + (size_t)(aRow0 + row) * Kin + (c2 << 2);
    const float* wRow = Wt + (size_t)(wRow0 + row) * Kin + (c2 << 2);
    const int base128 = (row >> 1) << 5;
    const int xr = (row >> 1) & 7;
    const int rb = (row & 1) << 2;
    const int dA0 = base128 + (((rb |  c2)      ^ xr) << 2);
    const int dA1 = base128 + (((rb | (c2 + 1)) ^ xr) << 2);

    float acc[4][4][4];
#pragma unroll
    for (int mt = 0; mt < 4; mt++)
#pragma unroll
        for (int nt = 0; nt < 4; nt++)
#pragma unroll
            for (int i = 0; i < 4; i++) acc[mt][nt][i] = 0.f;

    const int nk = Kin / 16;

    // prologue: prefetch tiles 0..NSTAGE-2
#pragma unroll
    for (int s = 0; s < NSTAGE - 1; s++) {
        float* ad = Asf + s * TILEF;
        float* bd = Bsf + s * TILEF;
        const float* ag = aRow + s * 16;
        const float* bg = wRow + s * 16;
        cpasync16(ad + dA0, ag);
        cpasync16(ad + dA1, ag + 4);
        cpasync16(bd + dA0, bg);
        cpasync16(bd + dA1, bg + 4);
        asm volatile("cp.async.commit_group;");
    }

    int buf = 0, pbuf = NSTAGE - 1;
    for (int kt = 0; kt < nk; kt++) {
        asm volatile("cp.async.wait_group %0;" :: "n"(NSTAGE - 2));
        __syncthreads();   // single barrier per k-tile

        // prefetch tile kt+NSTAGE-1 (targets buffer read at kt-1; safe post-barrier)
        int pf = kt + NSTAGE - 1;
        if (pf < nk) {
            float* ad = Asf + pbuf * TILEF;
            float* bd = Bsf + pbuf * TILEF;
            const float* ag = aRow + pf * 16;
            const float* bg = wRow + pf * 16;
            cpasync16(ad + dA0, ag);
            cpasync16(ad + dA1, ag + 4);
            cpasync16(bd + dA0, bg);
            cpasync16(bd + dA1, bg + 4);
        }
        asm volatile("cp.async.commit_group;");
        if (++pbuf == NSTAGE) pbuf = 0;

        const unsigned* as = (const unsigned*)(Asf + buf * TILEF);
        const unsigned* bs = (const unsigned*)(Bsf + buf * TILEF);
        if (++buf == NSTAGE) buf = 0;

#pragma unroll
        for (int ks = 0; ks < 2; ks++) {
            unsigned af[4][4], bf[4][2];
            const int col = ks * 8 + c0;
#pragma unroll
            for (int mt = 0; mt < 4; mt++) {
                int r = wm + mt * 16 + r0;
                af[mt][0] = as[swoff(r,     col)];
                af[mt][1] = as[swoff(r + 8, col)];
                af[mt][2] = as[swoff(r,     col + 4)];
                af[mt][3] = as[swoff(r + 8, col + 4)];
            }
#pragma unroll
            for (int nt = 0; nt < 4; nt++) {
                int r = wn + nt * 8 + r0;
                bf[nt][0] = bs[swoff(r, col)];
                bf[nt][1] = bs[swoff(r, col + 4)];
            }
#pragma unroll
            for (int mt = 0; mt < 4; mt++)
#pragma unroll
                for (int nt = 0; nt < 4; nt++)
                    mma8(acc[mt][nt], af[mt], bf[nt][0], bf[nt][1]);
        }
    }

    // epilogue
#pragma unroll
    for (int mt = 0; mt < 4; mt++) {
        int rl = wm + mt * 16 + r0;
#pragma unroll
        for (int nt = 0; nt < 4; nt++) {
            int cc = cCol0 + wn + nt * 8 + 2 * c0;
            float2 v0 = make_float2(acc[mt][nt][0], acc[mt][nt][1]);
            float2 v1 = make_float2(acc[mt][nt][2], acc[mt][nt][3]);
            if (mode == 1) {
                float2 u0 = *(const float2*)&R[(size_t)(rRow0 + rl) * NoutC + cc];
                float2 u1 = *(const float2*)&R[(size_t)(rRow0 + rl + 8) * NoutC + cc];
                v0.x += u0.x; v0.y += u0.y;
                v1.x += u1.x; v1.y += u1.y;
            } else if (mode == 2) {
                float2 u0 = *(const float2*)&R[(size_t)(rRow0 + rl) * NoutC + cc];
                float2 u1 = *(const float2*)&R[(size_t)(rRow0 + rl + 8) * NoutC + cc];
                v0.x = roundtf(v0.x * gelu_t(u0.x)); v0.y = roundtf(v0.y * gelu_t(u0.y));
                v1.x = roundtf(v1.x * gelu_t(u1.x)); v1.y = roundtf(v1.y * gelu_t(u1.y));
            }
            *(float2*)&C[(size_t)(cRow0 + rl) * NoutC + cc]     = v0;
            *(float2*)&C[(size_t)(cRow0 + rl + 8) * NoutC + cc] = v1;
        }
    }
}

// -------- fused QKV: grid (32 n-tiles, 16 m-tiles, 2 segments) ------------
__global__ __launch_bounds__(256, 2)
void qkv_tc()
{
    __shared__ float As[NSTAGE * TILEF];
    __shared__ float Bs[NSTAGE * TILEF];
    int bn = blockIdx.x, bm = blockIdx.y * 128, z = blockIdx.z;
    const float* wseg = g_wts + (size_t)z * WSEG;
    const float* Wt;
    float* C;
    int NoutC, wRow0;
    if (bn < 16) {
        Wt = wseg;                 C = g_q; NoutC = Nh * Hd; wRow0 = bn * 128;
    } else if (bn < 24) {
        Wt = wseg + WQ;            C = g_k; NoutC = Kh * Hd; wRow0 = (bn - 16) * 128;
    } else {
        Wt = wseg + WQ + WK;       C = g_v; NoutC = Kh * Hd; wRow0 = (bn - 24) * 128;
    }
    int rowTOT = bm + (bm >> 10) * 1024 + z * 1024;
    gemm_body(g_pre, Wt, C, nullptr, Dm, NoutC,
              rowTOT, wRow0, rowTOT, 0, wRow0, 0, As, Bs);
}

// -------- generic fused-2-segment GEMM ------------------------------------
// wOff: offset of this weight within per-seg block of g_wts
// row layout codes: 0 = [B,TOT] interleaved ; 1 = contiguous per-seg ; 2 = per-seg local
__global__ __launch_bounds__(256, 2)
void gemm_z(const float* __restrict__ A, size_t wOff,
            float* __restrict__ C,
            const float* __restrict__ R0, const float* __restrict__ R1,
            int Kin, int NoutC, int mode, int aLay, int cLay, int rLay)
{
    __shared__ float As[NSTAGE * TILEF];
    __shared__ float Bs[NSTAGE * TILEF];
    int bn = blockIdx.x, bm = blockIdx.y * 128, z = blockIdx.z;
    const float* Wt = g_wts + (size_t)z * WSEG + wOff;
    const float* R  = z ? R1 : R0;
    int rowTOT = bm + (bm >> 10) * 1024 + z * 1024;
    int rowSEG = z * 2048 + bm;
    int aRow0 = (aLay == 0) ? rowTOT : (aLay == 1 ? rowSEG : bm);
    int cRow0 = (cLay == 0) ? rowTOT : (cLay == 1 ? rowSEG : bm);
    int rRow0 = (rLay == 0) ? rowTOT : (rLay == 1 ? rowSEG : bm);
    gemm_body(A, Wt, C, R, Kin, NoutC,
              aRow0, bn * 128, cRow0, rRow0, bn * 128, mode, As, Bs);
}

// ---------------- attention: flash-style, tf32 mma ----------------
#define ATQ 64
#define ATS 32
#define KVP 136
#define PSP 36
__global__ __launch_bounds__(128, 2)
void attn_tc(const float* __restrict__ Q, const float* __restrict__ Kb,
             const float* __restrict__ Vb, float* __restrict__ enc)
{
    __shared__ unsigned Ks[ATS * KVP];
    __shared__ unsigned Vs[ATS * KVP];
    __shared__ unsigned Ps[4][16 * PSP];

    const int b = blockIdx.z, n = blockIdx.y;
    const int tq0 = blockIdx.x * ATQ;
    const int kh = n >> 1;   // G = 2
    const int tid = threadIdx.x, warp = tid >> 5, lane = tid & 31;
    const int r0 = lane >> 2, c0 = lane & 3;
    const int trowA = tq0 + warp * 16 + r0;

    unsigned qf[16][4];
    {
        const float* qbase = Q + ((size_t)(b * TOTc + tq0 + warp * 16)) * (Nh * Hd)
                               + (size_t)n * Hd;
        const size_t rs = (size_t)Nh * Hd;
#pragma unroll
        for (int hc = 0; hc < 16; hc++) {
            int col = hc * 8 + c0;
            const float* p0 = qbase + (size_t)r0 * rs + col;
            const float* p1 = qbase + (size_t)(r0 + 8) * rs + col;
            qf[hc][0] = f2tf32(p0[0]);
            qf[hc][1] = f2tf32(p1[0]);
            qf[hc][2] = f2tf32(p0[4]);
            qf[hc][3] = f2tf32(p1[4]);
        }
    }

    float oacc[16][4];
#pragma unroll
    for (int ht = 0; ht < 16; ht++)
#pragma unroll
        for (int i = 0; i < 4; i++) oacc[ht][i] = 0.f;
    float mA = -3.0e38f, mB = -3.0e38f, lA = 0.f, lB = 0.f;

    const int tmax = tq0 + ATQ - 1;

    for (int s0 = 0; s0 <= tmax; s0 += ATS) {
        for (int i = tid; i < ATS * Hd / 4; i += 128) {
            int sr = (i * 4) >> 7;
            int cl = (i * 4) & 127;
            size_t g = ((size_t)(b * TOTc + s0 + sr)) * (Kh * Hd) + (size_t)kh * Hd + cl;
            float4 kv = *(const float4*)&Kb[g];
            float4 vv = *(const float4*)&Vb[g];
            *(uint4*)&Ks[sr * KVP + cl] =
                make_uint4(f2tf32(kv.x), f2tf32(kv.y), f2tf32(kv.z), f2tf32(kv.w));
            *(uint4*)&Vs[sr * KVP + cl] =
                make_uint4(f2tf32(vv.x), f2tf32(vv.y), f2tf32(vv.z), f2tf32(vv.w));
        }
        __syncthreads();

        float sacc[4][4];
#pragma unroll
        for (int nt = 0; nt < 4; nt++)
#pragma unroll
            for (int i = 0; i < 4; i++) sacc[nt][i] = 0.f;
#pragma unroll
        for (int hc = 0; hc < 16; hc++) {
#pragma unroll
            for (int nt = 0; nt < 4; nt++) {
                unsigned b0 = Ks[(nt * 8 + r0) * KVP + hc * 8 + c0];
                unsigned b1 = Ks[(nt * 8 + r0) * KVP + hc * 8 + c0 + 4];
                mma8(sacc[nt], qf[hc], b0, b1);
            }
        }

        if (s0 + ATS - 1 > tq0 + warp * 16) {
#pragma unroll
            for (int nt = 0; nt < 4; nt++) {
                int sA = s0 + nt * 8 + 2 * c0;
                if (sA     > trowA)     sacc[nt][0] = -3.0e38f;
                if (sA + 1 > trowA)     sacc[nt][1] = -3.0e38f;
                if (sA     > trowA + 8) sacc[nt][2] = -3.0e38f;
                if (sA + 1 > trowA + 8) sacc[nt][3] = -3.0e38f;
            }
        }

        float mx0 = fmaxf(fmaxf(sacc[0][0], sacc[0][1]), fmaxf(sacc[1][0], sacc[1][1]));
        mx0 = fmaxf(mx0, fmaxf(fmaxf(sacc[2][0], sacc[2][1]), fmaxf(sacc[3][0], sacc[3][1])));
        float mx1 = fmaxf(fmaxf(sacc[0][2], sacc[0][3]), fmaxf(sacc[1][2], sacc[1][3]));
        mx1 = fmaxf(mx1, fmaxf(fmaxf(sacc[2][2], sacc[2][3]), fmaxf(sacc[3][2], sacc[3][3])));
#pragma unroll
        for (int o = 1; o <= 2; o <<= 1) {
            mx0 = fmaxf(mx0, __shfl_xor_sync(0xffffffffu, mx0, o));
            mx1 = fmaxf(mx1, __shfl_xor_sync(0xffffffffu, mx1, o));
        }
        float nmA = fmaxf(mA, mx0), nmB = fmaxf(mB, mx1);
        float scA = __expf(mA - nmA), scB = __expf(mB - nmB);
        mA = nmA; mB = nmB;

        float s0A = 0.f, s0B = 0.f;
        unsigned* pw = Ps[warp];
#pragma unroll
        for (int nt = 0; nt < 4; nt++) {
            float p0 = __expf(sacc[nt][0] - nmA);
            float p1 = __expf(sacc[nt][1] - nmA);
            float p2 = __expf(sacc[nt][2] - nmB);
            float p3 = __expf(sacc[nt][3] - nmB);
            s0A += p0 + p1; s0B += p2 + p3;
            int col = nt * 8 + 2 * c0;
            pw[r0 * PSP + col]           = f2tf32(p0);
            pw[r0 * PSP + col + 1]       = f2tf32(p1);
            pw[(r0 + 8) * PSP + col]     = f2tf32(p2);
            pw[(r0 + 8) * PSP + col + 1] = f2tf32(p3);
        }
#pragma unroll
        for (int o = 1; o <= 2; o <<= 1) {
            s0A += __shfl_xor_sync(0xffffffffu, s0A, o);
            s0B += __shfl_xor_sync(0xffffffffu, s0B, o);
        }
        lA = lA * scA + s0A;
        lB = lB * scB + s0B;

#pragma unroll
        for (int ht = 0; ht < 16; ht++) {
            oacc[ht][0] *= scA; oacc[ht][1] *= scA;
            oacc[ht][2] *= scB; oacc[ht][3] *= scB;
        }
        __syncwarp();

#pragma unroll
        for (int kc = 0; kc < 4; kc++) {
            unsigned af[4];
            af[0] = pw[r0 * PSP + kc * 8 + c0];
            af[1] = pw[(r0 + 8) * PSP + kc * 8 + c0];
            af[2] = pw[r0 * PSP + kc * 8 + c0 + 4];
            af[3] = pw[(r0 + 8) * PSP + kc * 8 + c0 + 4];
#pragma unroll
            for (int ht = 0; ht < 16; ht++) {
                unsigned b0 = Vs[(kc * 8 + c0) * KVP + ht * 8 + r0];
                unsigned b1 = Vs[(kc * 8 + c0 + 4) * KVP + ht * 8 + r0];
                mma8(oacc[ht], af, b0, b1);
            }
        }
        __syncthreads();
    }

    // output rounded to tf32 grid (enc is a GEMM A-input downstream)
    float invA = 1.f / lA, invB = 1.f / lB;
    const size_t baseA = ((size_t)(b * TOTc + trowA)) * (Nh * Hd) + (size_t)n * Hd;
    const size_t baseB = ((size_t)(b * TOTc + trowA + 8)) * (Nh * Hd) + (size_t)n * Hd;
#pragma unroll
    for (int ht = 0; ht < 16; ht++) {
        int cc = ht * 8 + 2 * c0;
        *(float2*)&enc[baseA + cc] =
            make_float2(roundtf(oacc[ht][0] * invA), roundtf(oacc[ht][1] * invA));
        *(float2*)&enc[baseB + cc] =
            make_float2(roundtf(oacc[ht][2] * invB), roundtf(oacc[ht][3] * invB));
    }
}

// ---------------- host orchestration ----------------
extern "C" void kernel_launch(void* const* d_in, const int* in_sizes, int n_in,
                              void* d_out, int out_size)
{
    (void)in_sizes; (void)n_in; (void)out_size;
    const float* xs[2] = {(const float*)d_in[0], (const float*)d_in[1]};
    const int*   pos   = (const int*)d_in[2];
    // d_in[3] = mask: causal lower-triangular, computed in-kernel
    const float* qw[2] = {(const float*)d_in[4],  (const float*)d_in[5]};
    const float* kw[2] = {(const float*)d_in[6],  (const float*)d_in[7]};
    const float* vw[2] = {(const float*)d_in[8],  (const float*)d_in[9]};
    const float* ow[2] = {(const float*)d_in[10], (const float*)d_in[11]};
    const float* gw[2] = {(const float*)d_in[12], (const float*)d_in[13]};
    const float* uw[2] = {(const float*)d_in[14], (const float*)d_in[15]};
    const float* dwn[2]= {(const float*)d_in[16], (const float*)d_in[17]};
    const float* pa[2] = {(const float*)d_in[18], (const float*)d_in[19]};
    const float* pf[2] = {(const float*)d_in[20], (const float*)d_in[21]};
    float* out = (float*)d_out;

    float *pre, *qb, *kb, *vb, *enc, *res, *hid, *gu, *wts;
    cudaGetSymbolAddress((void**)&pre, g_pre);
    cudaGetSymbolAddress((void**)&qb,  g_q);
    cudaGetSymbolAddress((void**)&kb,  g_k);
    cudaGetSymbolAddress((void**)&vb,  g_v);
    cudaGetSymbolAddress((void**)&enc, g_enc);
    cudaGetSymbolAddress((void**)&res, g_res);
    cudaGetSymbolAddress((void**)&hid, g_hid);
    cudaGetSymbolAddress((void**)&gu,  g_gu);
    cudaGetSymbolAddress((void**)&wts, g_wts);

    const int Ts[2]   = {T0c, T1c};
    const int offs[2] = {0, T0c};

    // 0) round weights to tf32 grid once (idempotent, deterministic)
    const float* srcs[7 * 2];
    size_t sizes[7], woffs[7];
    sizes[0] = WQ; sizes[1] = WK; sizes[2] = WK; sizes[3] = WQ;
    sizes[4] = WF; sizes[5] = WF; sizes[6] = WF;
    woffs[0] = 0;
    for (int i = 1; i < 7; i++) woffs[i] = woffs[i - 1] + sizes[i - 1];
    for (int z = 0; z < 2; z++) {
        srcs[z * 7 + 0] = qw[z];  srcs[z * 7 + 1] = kw[z];  srcs[z * 7 + 2] = vw[z];
        srcs[z * 7 + 3] = ow[z];  srcs[z * 7 + 4] = gw[z];  srcs[z * 7 + 5] = uw[z];
        srcs[z * 7 + 6] = dwn[z];
    }
    for (int z = 0; z < 2; z++)
        for (int i = 0; i < 7; i++) {
            int n4 = (int)(sizes[i] / 4);
            roundcp_k<<<(n4 + 255) / 256, 256>>>(
                (const float4*)srcs[z * 7 + i],
                (float4*)(wts + (size_t)z * WSEG + woffs[i]), n4);
        }

    // 1) pre-attention RMSNorm (rounded output)
    for (int s = 0; s < 2; s++)
        rmsnorm_k<<<Bb * Ts[s], 256>>>(xs[s], pa[s], pre,
                                       Ts[s], Ts[s], 0, Ts[s], TOTc, offs[s]);

    // 2) fused QKV projection, both segments
    qkv_tc<<<dim3(32, 16, 2), 256>>>();

    // 3) RoPE (Q gets 1/sqrt(H) folded in)
    rope_k<<<Bb * TOTc * Nh, 64>>>(qb, pos, Nh, 0.08838834764831845f);
    rope_k<<<Bb * TOTc * Kh, 64>>>(kb, pos, Kh, 1.0f);

    // 4) attention (tensor-core flash; rounded output)
    attn_tc<<<dim3(TOTc / ATQ, Nh, Bb), 128>>>(qb, kb, vb, enc);

    // 5) O projection + residual add of x
    gemm_z<<<dim3(Dm / 128, 16, 2), 256>>>(enc, woffs[3], res, xs[0], xs[1],
                                           Nh * Hd, Dm, 1, 0, 0, 2);

    // 6) pre-FFN RMSNorm (rounded output)
    for (int s = 0; s < 2; s++)
        rmsnorm_k<<<Bb * Ts[s], 256>>>(res, pf[s], hid,
                                       Ts[s], TOTc, offs[s], Ts[s], TOTc, offs[s]);

    // 7) FFN: gate -> gu ; up (epilogue round(gelu(gate)*up)) -> gu ; down + res -> out
    gemm_z<<<dim3(Ff / 128, 16, 2), 256>>>(hid, woffs[4], gu, nullptr, nullptr,
                                           Dm, Ff, 0, 0, 1, 1);
    gemm_z<<<dim3(Ff / 128, 16, 2), 256>>>(hid, woffs[5], gu, gu, gu,
                                           Dm, Ff, 2, 0, 1, 1);
    gemm_z<<<dim3(Dm / 128, 16, 2), 256>>>(gu, woffs[6], out, res, res,
                                           Ff, Dm, 1, 1, 1, 0);
}

// round 6
// speedup vs baseline: 1.5586x; 1.2756x over previous
#include <cuda_runtime.h>
#include <math.h>
#include <stdint.h>

// Problem constants
#define Dm   2048
#define Nh   16
#define Kh   8
#define Hd   128
#define Ff   8192
#define Bb   2
#define T0c  1024
#define T1c  1024
#define TOTc 2048

// ---------------- scratch (static device globals; no allocation) ----------
__device__ float g_pre [(size_t)Bb*TOTc*Dm];
__device__ float g_q   [(size_t)Bb*TOTc*Nh*Hd];
__device__ float g_k   [(size_t)Bb*TOTc*Kh*Hd];
__device__ float g_v   [(size_t)Bb*TOTc*Kh*Hd];
__device__ float g_enc [(size_t)Bb*TOTc*Nh*Hd];
__device__ float g_res [(size_t)Bb*TOTc*Dm];
__device__ float g_hid [(size_t)Bb*TOTc*Dm];
__device__ float g_gu  [(size_t)2*Bb*T0c*Ff];
// rounded weight copies (tf32-RNA applied once)
#define WQ  (2048 * 2048)
#define WK  (1024 * 2048)
#define WF  (8192 * 2048)
#define WSEG (WQ + WK + WK + WQ + WF + WF + WF)
__device__ float g_wts [(size_t)2 * WSEG];

__device__ __forceinline__ unsigned f2tf32(float x) {
    unsigned r;
    asm("cvt.rna.tf32.f32 %0, %1;" : "=r"(r) : "f"(x));
    return r;
}
__device__ __forceinline__ float roundtf(float x) {
    return __uint_as_float(f2tf32(x));
}

__device__ __forceinline__ void mma8(float* c, const unsigned* a, unsigned b0, unsigned b1) {
    asm volatile(
        "mma.sync.aligned.m16n8k8.row.col.f32.tf32.tf32.f32 "
        "{%0,%1,%2,%3},{%4,%5,%6,%7},{%8,%9},{%0,%1,%2,%3};"
        : "+f"(c[0]), "+f"(c[1]), "+f"(c[2]), "+f"(c[3])
        : "r"(a[0]), "r"(a[1]), "r"(a[2]), "r"(a[3]), "r"(b0), "r"(b1));
}

__device__ __forceinline__ void ldsm4(unsigned& d0, unsigned& d1, unsigned& d2, unsigned& d3,
                                      unsigned saddr) {
    asm volatile("ldmatrix.sync.aligned.m8n8.x4.shared.b16 {%0,%1,%2,%3}, [%4];"
                 : "=r"(d0), "=r"(d1), "=r"(d2), "=r"(d3) : "r"(saddr));
}

__device__ __forceinline__ float gelu_t(float x) {
    float x3 = x * x * x;
    float t = tanhf(0.7978845608028654f * (x + 0.044715f * x3));
    return 0.5f * x * (1.f + t);
}

__device__ __forceinline__ void cpasync16(float* s, const float* g) {
    unsigned saddr = (unsigned)__cvta_generic_to_shared(s);
    asm volatile("cp.async.cg.shared.global [%0], [%1], 16;" :: "r"(saddr), "l"(g));
}

// swizzled float offset for element (row r, col c) in a 128x16 tile
__device__ __forceinline__ int swoff(int r, int c) {
    return ((r >> 1) << 5) + (((((r & 1) << 2) | (c >> 2)) ^ ((r >> 1) & 7)) << 2) + (c & 3);
}

// ---------------- weight rounding prep ----------------
__global__ void roundcp_k(const float4* __restrict__ in, float4* __restrict__ out, int n4)
{
    int i = blockIdx.x * 256 + threadIdx.x;
    if (i >= n4) return;
    float4 v = in[i];
    v.x = roundtf(v.x); v.y = roundtf(v.y);
    v.z = roundtf(v.z); v.w = roundtf(v.w);
    out[i] = v;
}

// ---------------- RMSNorm (output rounded to tf32 grid) ----------------
__device__ __forceinline__ int maprow(int r, int T, int TT, int off) {
    return (r / T) * TT + (r % T) + off;
}

__global__ void rmsnorm_k(const float* __restrict__ x, const float* __restrict__ sc,
                          float* __restrict__ out,
                          int iT, int iTT, int iOff, int oT, int oTT, int oOff)
{
    int r = blockIdx.x;
    const float* xi = x + (size_t)maprow(r, iT, iTT, iOff) * Dm;
    float* o = out + (size_t)maprow(r, oT, oTT, oOff) * Dm;
    __shared__ float red[256];
    float s = 0.f;
    for (int d = threadIdx.x; d < Dm; d += 256) { float v = xi[d]; s += v * v; }
    red[threadIdx.x] = s;
    __syncthreads();
    for (int st = 128; st > 0; st >>= 1) {
        if (threadIdx.x < st) red[threadIdx.x] += red[threadIdx.x + st];
        __syncthreads();
    }
    float inv = rsqrtf(red[0] / (float)Dm + 1e-6f);
    for (int d = threadIdx.x; d < Dm; d += 256)
        o[d] = roundtf(xi[d] * inv * (1.f + sc[d]));
}

// ---------------- RoPE ----------------
__global__ void rope_k(float* __restrict__ x, const int* __restrict__ pos,
                       int nheads, float scale)
{
    int blk  = blockIdx.x;
    int head = blk % nheads;
    int bt   = blk / nheads;
    float p  = (float)pos[bt];
    float* v = x + ((size_t)bt * nheads + head) * Hd;
    int h = threadIdx.x;               // 0..63
    float fe = (2.f / (float)Hd) * (float)h;
    float inv_ts = exp2f(-fe * 13.287712379549449f);
    float rad = p * inv_ts;
    float s, c;
    sincosf(rad, &s, &c);
    float x1 = v[h], x2 = v[h + 64];
    v[h]      = (x1 * c - x2 * s) * scale;
    v[h + 64] = (x2 * c + x1 * s) * scale;
}

// ---------------- tf32 GEMM body: cp.async 3-stage + ldmatrix fragments ----
// CTA tile 128x128, BK=16. 8 warps = 2m x 4n, warp tile 64x32.
// mode: 0 = C=acc ; 1 = C=acc+R ; 2 = C=round(gelu(R)*acc)
#define NSTAGE 3
#define TILEF  (128 * 16)
__device__ __forceinline__ void gemm_body(
    const float* __restrict__ A, const float* __restrict__ Wt,
    float* __restrict__ C, const float* __restrict__ R,
    int Kin, int NoutC,
    int aRow0, int wRow0, int cRow0, int rRow0, int cCol0, int mode,
    float* __restrict__ Asf, float* __restrict__ Bsf)
{
    const int tid  = threadIdx.x;
    const int warp = tid >> 5, lane = tid & 31;
    const int wm   = (warp & 1) * 64;
    const int wn   = (warp >> 1) * 32;
    const int r0   = lane >> 2, c0 = lane & 3;

    // cp.async mapping: thread t -> row t>>1, two 16B chunks
    const int row = tid >> 1;
    const int c2  = (tid & 1) << 1;
    const float* aRow = A  + (size_t)(aRow0 + row) * Kin + (c2 << 2);
    const float* wRow = Wt + (size_t)(wRow0 + row) * Kin + (c2 << 2);
    const int base128 = (row >> 1) << 5;
    const int xr = (row >> 1) & 7;
    const int rb = (row & 1) << 2;
    const int dA0 = base128 + (((rb |  c2)      ^ xr) << 2);
    const int dA1 = base128 + (((rb | (c2 + 1)) ^ xr) << 2);

    // ldmatrix per-thread address deltas (bytes, loop-invariant)
    const int sub  = lane >> 3;      // quadrant index within x4
    const int lrow = lane & 7;       // row fed by this thread
    unsigned aDel[4][2], bDel[2][2];
#pragma unroll
    for (int mt = 0; mt < 4; mt++)
#pragma unroll
        for (int ks = 0; ks < 2; ks++) {
            int r  = wm + mt * 16 + ((sub & 1) << 3) + lrow;
            int ch = ks * 2 + (sub >> 1);
            aDel[mt][ks] = (unsigned)(swoff(r, ch << 2) << 2);
        }
#pragma unroll
    for (int p = 0; p < 2; p++)
#pragma unroll
        for (int ks = 0; ks < 2; ks++) {
            int nt = p * 2 + (sub >> 1);
            int r  = wn + nt * 8 + lrow;
            int ch = ks * 2 + (sub & 1);
            bDel[p][ks] = (unsigned)(swoff(r, ch << 2) << 2);
        }

    const unsigned asBase = (unsigned)__cvta_generic_to_shared(Asf);
    const unsigned bsBase = (unsigned)__cvta_generic_to_shared(Bsf);

    float acc[4][4][4];
#pragma unroll
    for (int mt = 0; mt < 4; mt++)
#pragma unroll
        for (int nt = 0; nt < 4; nt++)
#pragma unroll
            for (int i = 0; i < 4; i++) acc[mt][nt][i] = 0.f;

    const int nk = Kin / 16;

    // prologue: prefetch tiles 0..NSTAGE-2
#pragma unroll
    for (int s = 0; s < NSTAGE - 1; s++) {
        float* ad = Asf + s * TILEF;
        float* bd = Bsf + s * TILEF;
        const float* ag = aRow + s * 16;
        const float* bg = wRow + s * 16;
        cpasync16(ad + dA0, ag);
        cpasync16(ad + dA1, ag + 4);
        cpasync16(bd + dA0, bg);
        cpasync16(bd + dA1, bg + 4);
        asm volatile("cp.async.commit_group;");
    }

    int buf = 0, pbuf = NSTAGE - 1;
    for (int kt = 0; kt < nk; kt++) {
        asm volatile("cp.async.wait_group %0;" :: "n"(NSTAGE - 2));
        __syncthreads();   // single barrier per k-tile

        int pf = kt + NSTAGE - 1;
        if (pf < nk) {
            float* ad = Asf + pbuf * TILEF;
            float* bd = Bsf + pbuf * TILEF;
            const float* ag = aRow + pf * 16;
            const float* bg = wRow + pf * 16;
            cpasync16(ad + dA0, ag);
            cpasync16(ad + dA1, ag + 4);
            cpasync16(bd + dA0, bg);
            cpasync16(bd + dA1, bg + 4);
        }
        asm volatile("cp.async.commit_group;");
        if (++pbuf == NSTAGE) pbuf = 0;

        const unsigned aB = asBase + (unsigned)(buf * TILEF * 4);
        const unsigned bB = bsBase + (unsigned)(buf * TILEF * 4);
        if (++buf == NSTAGE) buf = 0;

#pragma unroll
        for (int ks = 0; ks < 2; ks++) {
            unsigned af[4][4], bf[4][2];
#pragma unroll
            for (int mt = 0; mt < 4; mt++)
                ldsm4(af[mt][0], af[mt][1], af[mt][2], af[mt][3], aB + aDel[mt][ks]);
#pragma unroll
            for (int p = 0; p < 2; p++)
                ldsm4(bf[2*p][0], bf[2*p][1], bf[2*p+1][0], bf[2*p+1][1], bB + bDel[p][ks]);
#pragma unroll
            for (int mt = 0; mt < 4; mt++)
#pragma unroll
                for (int nt = 0; nt < 4; nt++)
                    mma8(acc[mt][nt], af[mt], bf[nt][0], bf[nt][1]);
        }
    }

    // epilogue
#pragma unroll
    for (int mt = 0; mt < 4; mt++) {
        int rl = wm + mt * 16 + r0;
#pragma unroll
        for (int nt = 0; nt < 4; nt++) {
            int cc = cCol0 + wn + nt * 8 + 2 * c0;
            float2 v0 = make_float2(acc[mt][nt][0], acc[mt][nt][1]);
            float2 v1 = make_float2(acc[mt][nt][2], acc[mt][nt][3]);
            if (mode == 1) {
                float2 u0 = *(const float2*)&R[(size_t)(rRow0 + rl) * NoutC + cc];
                float2 u1 = *(const float2*)&R[(size_t)(rRow0 + rl + 8) * NoutC + cc];
                v0.x += u0.x; v0.y += u0.y;
                v1.x += u1.x; v1.y += u1.y;
            } else if (mode == 2) {
                float2 u0 = *(const float2*)&R[(size_t)(rRow0 + rl) * NoutC + cc];
                float2 u1 = *(const float2*)&R[(size_t)(rRow0 + rl + 8) * NoutC + cc];
                v0.x = roundtf(v0.x * gelu_t(u0.x)); v0.y = roundtf(v0.y * gelu_t(u0.y));
                v1.x = roundtf(v1.x * gelu_t(u1.x)); v1.y = roundtf(v1.y * gelu_t(u1.y));
            }
            *(float2*)&C[(size_t)(cRow0 + rl) * NoutC + cc]     = v0;
            *(float2*)&C[(size_t)(cRow0 + rl + 8) * NoutC + cc] = v1;
        }
    }
}

// -------- fused QKV: grid (32 n-tiles, 16 m-tiles, 2 segments) ------------
__global__ __launch_bounds__(256, 2)
void qkv_tc()
{
    __shared__ __align__(16) float As[NSTAGE * TILEF];
    __shared__ __align__(16) float Bs[NSTAGE * TILEF];
    int bn = blockIdx.x, bm = blockIdx.y * 128, z = blockIdx.z;
    const float* wseg = g_wts + (size_t)z * WSEG;
    const float* Wt;
    float* C;
    int NoutC, wRow0;
    if (bn < 16) {
        Wt = wseg;                 C = g_q; NoutC = Nh * Hd; wRow0 = bn * 128;
    } else if (bn < 24) {
        Wt = wseg + WQ;            C = g_k; NoutC = Kh * Hd; wRow0 = (bn - 16) * 128;
    } else {
        Wt = wseg + WQ + WK;       C = g_v; NoutC = Kh * Hd; wRow0 = (bn - 24) * 128;
    }
    int rowTOT = bm + (bm >> 10) * 1024 + z * 1024;
    gemm_body(g_pre, Wt, C, nullptr, Dm, NoutC,
              rowTOT, wRow0, rowTOT, 0, wRow0, 0, As, Bs);
}

// -------- generic fused-2-segment GEMM ------------------------------------
__global__ __launch_bounds__(256, 2)
void gemm_z(const float* __restrict__ A, size_t wOff,
            float* __restrict__ C,
            const float* __restrict__ R0, const float* __restrict__ R1,
            int Kin, int NoutC, int mode, int aLay, int cLay, int rLay)
{
    __shared__ __align__(16) float As[NSTAGE * TILEF];
    __shared__ __align__(16) float Bs[NSTAGE * TILEF];
    int bn = blockIdx.x, bm = blockIdx.y * 128, z = blockIdx.z;
    const float* Wt = g_wts + (size_t)z * WSEG + wOff;
    const float* R  = z ? R1 : R0;
    int rowTOT = bm + (bm >> 10) * 1024 + z * 1024;
    int rowSEG = z * 2048 + bm;
    int aRow0 = (aLay == 0) ? rowTOT : (aLay == 1 ? rowSEG : bm);
    int cRow0 = (cLay == 0) ? rowTOT : (cLay == 1 ? rowSEG : bm);
    int rRow0 = (rLay == 0) ? rowTOT : (rLay == 1 ? rowSEG : bm);
    gemm_body(A, Wt, C, R, Kin, NoutC,
              aRow0, bn * 128, cRow0, rRow0, bn * 128, mode, As, Bs);
}

// ---------------- attention: flash-style, tf32 mma ----------------
#define ATQ 64
#define ATS 32
#define KVP 136
#define PSP 36
__global__ __launch_bounds__(128, 2)
void attn_tc(const float* __restrict__ Q, const float* __restrict__ Kb,
             const float* __restrict__ Vb, float* __restrict__ enc)
{
    __shared__ unsigned Ks[ATS * KVP];
    __shared__ unsigned Vs[ATS * KVP];
    __shared__ unsigned Ps[4][16 * PSP];

    const int b = blockIdx.z, n = blockIdx.y;
    const int tq0 = blockIdx.x * ATQ;
    const int kh = n >> 1;   // G = 2
    const int tid = threadIdx.x, warp = tid >> 5, lane = tid & 31;
    const int r0 = lane >> 2, c0 = lane & 3;
    const int trowA = tq0 + warp * 16 + r0;

    unsigned qf[16][4];
    {
        const float* qbase = Q + ((size_t)(b * TOTc + tq0 + warp * 16)) * (Nh * Hd)
                               + (size_t)n * Hd;
        const size_t rs = (size_t)Nh * Hd;
#pragma unroll
        for (int hc = 0; hc < 16; hc++) {
            int col = hc * 8 + c0;
            const float* p0 = qbase + (size_t)r0 * rs + col;
            const float* p1 = qbase + (size_t)(r0 + 8) * rs + col;
            qf[hc][0] = f2tf32(p0[0]);
            qf[hc][1] = f2tf32(p1[0]);
            qf[hc][2] = f2tf32(p0[4]);
            qf[hc][3] = f2tf32(p1[4]);
        }
    }

    float oacc[16][4];
#pragma unroll
    for (int ht = 0; ht < 16; ht++)
#pragma unroll
        for (int i = 0; i < 4; i++) oacc[ht][i] = 0.f;
    float mA = -3.0e38f, mB = -3.0e38f, lA = 0.f, lB = 0.f;

    const int tmax = tq0 + ATQ - 1;

    for (int s0 = 0; s0 <= tmax; s0 += ATS) {
        for (int i = tid; i < ATS * Hd / 4; i += 128) {
            int sr = (i * 4) >> 7;
            int cl = (i * 4) & 127;
            size_t g = ((size_t)(b * TOTc + s0 + sr)) * (Kh * Hd) + (size_t)kh * Hd + cl;
            float4 kv = *(const float4*)&Kb[g];
            float4 vv = *(const float4*)&Vb[g];
            *(uint4*)&Ks[sr * KVP + cl] =
                make_uint4(f2tf32(kv.x), f2tf32(kv.y), f2tf32(kv.z), f2tf32(kv.w));
            *(uint4*)&Vs[sr * KVP + cl] =
                make_uint4(f2tf32(vv.x), f2tf32(vv.y), f2tf32(vv.z), f2tf32(vv.w));
        }
        __syncthreads();

        float sacc[4][4];
#pragma unroll
        for (int nt = 0; nt < 4; nt++)
#pragma unroll
            for (int i = 0; i < 4; i++) sacc[nt][i] = 0.f;
#pragma unroll
        for (int hc = 0; hc < 16; hc++) {
#pragma unroll
            for (int nt = 0; nt < 4; nt++) {
                unsigned b0 = Ks[(nt * 8 + r0) * KVP + hc * 8 + c0];
                unsigned b1 = Ks[(nt * 8 + r0) * KVP + hc * 8 + c0 + 4];
                mma8(sacc[nt], qf[hc], b0, b1);
            }
        }

        if (s0 + ATS - 1 > tq0 + warp * 16) {
#pragma unroll
            for (int nt = 0; nt < 4; nt++) {
                int sA = s0 + nt * 8 + 2 * c0;
                if (sA     > trowA)     sacc[nt][0] = -3.0e38f;
                if (sA + 1 > trowA)     sacc[nt][1] = -3.0e38f;
                if (sA     > trowA + 8) sacc[nt][2] = -3.0e38f;
                if (sA + 1 > trowA + 8) sacc[nt][3] = -3.0e38f;
            }
        }

        float mx0 = fmaxf(fmaxf(sacc[0][0], sacc[0][1]), fmaxf(sacc[1][0], sacc[1][1]));
        mx0 = fmaxf(mx0, fmaxf(fmaxf(sacc[2][0], sacc[2][1]), fmaxf(sacc[3][0], sacc[3][1])));
        float mx1 = fmaxf(fmaxf(sacc[0][2], sacc[0][3]), fmaxf(sacc[1][2], sacc[1][3]));
        mx1 = fmaxf(mx1, fmaxf(fmaxf(sacc[2][2], sacc[2][3]), fmaxf(sacc[3][2], sacc[3][3])));
#pragma unroll
        for (int o = 1; o <= 2; o <<= 1) {
            mx0 = fmaxf(mx0, __shfl_xor_sync(0xffffffffu, mx0, o));
            mx1 = fmaxf(mx1, __shfl_xor_sync(0xffffffffu, mx1, o));
        }
        float nmA = fmaxf(mA, mx0), nmB = fmaxf(mB, mx1);
        float scA = __expf(mA - nmA), scB = __expf(mB - nmB);
        mA = nmA; mB = nmB;

        float s0A = 0.f, s0B = 0.f;
        unsigned* pw = Ps[warp];
#pragma unroll
        for (int nt = 0; nt < 4; nt++) {
            float p0 = __expf(sacc[nt][0] - nmA);
            float p1 = __expf(sacc[nt][1] - nmA);
            float p2 = __expf(sacc[nt][2] - nmB);
            float p3 = __expf(sacc[nt][3] - nmB);
            s0A += p0 + p1; s0B += p2 + p3;
            int col = nt * 8 + 2 * c0;
            pw[r0 * PSP + col]           = f2tf32(p0);
            pw[r0 * PSP + col + 1]       = f2tf32(p1);
            pw[(r0 + 8) * PSP + col]     = f2tf32(p2);
            pw[(r0 + 8) * PSP + col + 1] = f2tf32(p3);
        }
#pragma unroll
        for (int o = 1; o <= 2; o <<= 1) {
            s0A += __shfl_xor_sync(0xffffffffu, s0A, o);
            s0B += __shfl_xor_sync(0xffffffffu, s0B, o);
        }
        lA = lA * scA + s0A;
        lB = lB * scB + s0B;

#pragma unroll
        for (int ht = 0; ht < 16; ht++) {
            oacc[ht][0] *= scA; oacc[ht][1] *= scA;
            oacc[ht][2] *= scB; oacc[ht][3] *= scB;
        }
        __syncwarp();

#pragma unroll
        for (int kc = 0; kc < 4; kc++) {
            unsigned af[4];
            af[0] = pw[r0 * PSP + kc * 8 + c0];
            af[1] = pw[(r0 + 8) * PSP + kc * 8 + c0];
            af[2] = pw[r0 * PSP + kc * 8 + c0 + 4];
            af[3] = pw[(r0 + 8) * PSP + kc * 8 + c0 + 4];
#pragma unroll
            for (int ht = 0; ht < 16; ht++) {
                unsigned b0 = Vs[(kc * 8 + c0) * KVP + ht * 8 + r0];
                unsigned b1 = Vs[(kc * 8 + c0 + 4) * KVP + ht * 8 + r0];
                mma8(oacc[ht], af, b0, b1);
            }
        }
        __syncthreads();
    }

    float invA = 1.f / lA, invB = 1.f / lB;
    const size_t baseA = ((size_t)(b * TOTc + trowA)) * (Nh * Hd) + (size_t)n * Hd;
    const size_t baseB = ((size_t)(b * TOTc + trowA + 8)) * (Nh * Hd) + (size_t)n * Hd;
#pragma unroll
    for (int ht = 0; ht < 16; ht++) {
        int cc = ht * 8 + 2 * c0;
        *(float2*)&enc[baseA + cc] =
            make_float2(roundtf(oacc[ht][0] * invA), roundtf(oacc[ht][1] * invA));
        *(float2*)&enc[baseB + cc] =
            make_float2(roundtf(oacc[ht][2] * invB), roundtf(oacc[ht][3] * invB));
    }
}

// ---------------- host orchestration ----------------
extern "C" void kernel_launch(void* const* d_in, const int* in_sizes, int n_in,
                              void* d_out, int out_size)
{
    (void)in_sizes; (void)n_in; (void)out_size;
    const float* xs[2] = {(const float*)d_in[0], (const float*)d_in[1]};
    const int*   pos   = (const int*)d_in[2];
    // d_in[3] = mask: causal lower-triangular, computed in-kernel
    const float* qw[2] = {(const float*)d_in[4],  (const float*)d_in[5]};
    const float* kw[2] = {(const float*)d_in[6],  (const float*)d_in[7]};
    const float* vw[2] = {(const float*)d_in[8],  (const float*)d_in[9]};
    const float* ow[2] = {(const float*)d_in[10], (const float*)d_in[11]};
    const float* gw[2] = {(const float*)d_in[12], (const float*)d_in[13]};
    const float* uw[2] = {(const float*)d_in[14], (const float*)d_in[15]};
    const float* dwn[2]= {(const float*)d_in[16], (const float*)d_in[17]};
    const float* pa[2] = {(const float*)d_in[18], (const float*)d_in[19]};
    const float* pf[2] = {(const float*)d_in[20], (const float*)d_in[21]};
    float* out = (float*)d_out;

    float *pre, *qb, *kb, *vb, *enc, *res, *hid, *gu, *wts;
    cudaGetSymbolAddress((void**)&pre, g_pre);
    cudaGetSymbolAddress((void**)&qb,  g_q);
    cudaGetSymbolAddress((void**)&kb,  g_k);
    cudaGetSymbolAddress((void**)&vb,  g_v);
    cudaGetSymbolAddress((void**)&enc, g_enc);
    cudaGetSymbolAddress((void**)&res, g_res);
    cudaGetSymbolAddress((void**)&hid, g_hid);
    cudaGetSymbolAddress((void**)&gu,  g_gu);
    cudaGetSymbolAddress((void**)&wts, g_wts);

    const int Ts[2]   = {T0c, T1c};
    const int offs[2] = {0, T0c};

    // 0) round weights to tf32 grid once per call (idempotent, deterministic)
    const float* srcs[7 * 2];
    size_t sizes[7], woffs[7];
    sizes[0] = WQ; sizes[1] = WK; sizes[2] = WK; sizes[3] = WQ;
    sizes[4] = WF; sizes[5] = WF; sizes[6] = WF;
    woffs[0] = 0;
    for (int i = 1; i < 7; i++) woffs[i] = woffs[i - 1] + sizes[i - 1];
    for (int z = 0; z < 2; z++) {
        srcs[z * 7 + 0] = qw[z];  srcs[z * 7 + 1] = kw[z];  srcs[z * 7 + 2] = vw[z];
        srcs[z * 7 + 3] = ow[z];  srcs[z * 7 + 4] = gw[z];  srcs[z * 7 + 5] = uw[z];
        srcs[z * 7 + 6] = dwn[z];
    }
    for (int z = 0; z < 2; z++)
        for (int i = 0; i < 7; i++) {
            int n4 = (int)(sizes[i] / 4);
            roundcp_k<<<(n4 + 255) / 256, 256>>>(
                (const float4*)srcs[z * 7 + i],
                (float4*)(wts + (size_t)z * WSEG + woffs[i]), n4);
        }

    // 1) pre-attention RMSNorm (rounded output)
    for (int s = 0; s < 2; s++)
        rmsnorm_k<<<Bb * Ts[s], 256>>>(xs[s], pa[s], pre,
                                       Ts[s], Ts[s], 0, Ts[s], TOTc, offs[s]);

    // 2) fused QKV projection, both segments
    qkv_tc<<<dim3(32, 16, 2), 256>>>();

    // 3) RoPE (Q gets 1/sqrt(H) folded in)
    rope_k<<<Bb * TOTc * Nh, 64>>>(qb, pos, Nh, 0.08838834764831845f);
    rope_k<<<Bb * TOTc * Kh, 64>>>(kb, pos, Kh, 1.0f);

    // 4) attention (tensor-core flash; rounded output)
    attn_tc<<<dim3(TOTc / ATQ, Nh, Bb), 128>>>(qb, kb, vb, enc);

    // 5) O projection + residual add of x
    gemm_z<<<dim3(Dm / 128, 16, 2), 256>>>(enc, woffs[3], res, xs[0], xs[1],
                                           Nh * Hd, Dm, 1, 0, 0, 2);

    // 6) pre-FFN RMSNorm (rounded output)
    for (int s = 0; s < 2; s++)
        rmsnorm_k<<<Bb * Ts[s], 256>>>(res, pf[s], hid,
                                       Ts[s], TOTc, offs[s], Ts[s], TOTc, offs[s]);

    // 7) FFN: gate -> gu ; up (epilogue round(gelu(gate)*up)) -> gu ; down + res -> out
    gemm_z<<<dim3(Ff / 128, 16, 2), 256>>>(hid, woffs[4], gu, nullptr, nullptr,
                                           Dm, Ff, 0, 0, 1, 1);
    gemm_z<<<dim3(Ff / 128, 16, 2), 256>>>(hid, woffs[5], gu, gu, gu,
                                           Dm, Ff, 2, 0, 1, 1);
    gemm_z<<<dim3(Dm / 128, 16, 2), 256>>>(gu, woffs[6], out, res, res,
                                           Ff, Dm, 1, 1, 1, 0);
}